// round 15
// baseline (speedup 1.0000x reference)
#include <cuda_runtime.h>
#include <cuda.h>
#include <cuda_fp16.h>
#include <math.h>
#include <stdint.h>

// Problem constants
#define Bd   4
#define Td   2048
#define Cd   1024
#define NHd  16
#define HSd  64
#define Md   (Bd * Td)          // 8192 rows
#define N_QKV (3 * Cd)          // 3072
#define KDIM Cd                 // 1024

// ---------------- scratch (device globals: allocation-free) ----------------
__device__ __align__(16) __half g_Q[Bd * NHd * Td * HSd];  // pre-scaled 0.125
__device__ __align__(16) __half g_K[Bd * NHd * Td * HSd];
__device__ __align__(16) __half g_V[Bd * NHd * Td * HSd];
__device__ __align__(16) __half g_Y[Md * Cd];              // attn out [B,T,C]
__device__ __align__(16) __half g_xh[Md * KDIM];           // fp16(x)       [M,K]
__device__ __align__(16) __half g_WAt[N_QKV * KDIM];       // fp16(W_attn^T)[N,K]
__device__ __align__(16) __half g_WPt[Cd * KDIM];          // fp16(W_proj^T)[N,K]
__device__ CUtensorMap d_tmaps[4];                         // X, WA, WP, Y

// ---------------- generic helpers -------------------------------------------
__device__ __forceinline__ uint32_t smem_u32(const void* p) {
    return (uint32_t)__cvta_generic_to_shared(p);
}
__device__ __forceinline__ uint32_t h2_bits(__half2 h) {
    return *reinterpret_cast<uint32_t*>(&h);
}
__device__ __forceinline__ uint32_t pack_h2(float a, float b) {
    return h2_bits(__floats2half2_rn(a, b));
}

__device__ __forceinline__ void ldm_x4(uint32_t r[4], uint32_t addr) {
    asm volatile("ldmatrix.sync.aligned.m8n8.x4.shared.b16 {%0,%1,%2,%3}, [%4];"
                 : "=r"(r[0]), "=r"(r[1]), "=r"(r[2]), "=r"(r[3]) : "r"(addr));
}
__device__ __forceinline__ void ldm_x4t(uint32_t r[4], uint32_t addr) {
    asm volatile("ldmatrix.sync.aligned.m8n8.x4.trans.shared.b16 {%0,%1,%2,%3}, [%4];"
                 : "=r"(r[0]), "=r"(r[1]), "=r"(r[2]), "=r"(r[3]) : "r"(addr));
}
__device__ __forceinline__ void mma_f16(float c[4], const uint32_t a[4],
                                        const uint32_t b[2]) {
    asm volatile(
        "mma.sync.aligned.m16n8k16.row.col.f32.f16.f16.f32 "
        "{%0,%1,%2,%3}, {%4,%5,%6,%7}, {%8,%9}, {%0,%1,%2,%3};"
        : "+f"(c[0]), "+f"(c[1]), "+f"(c[2]), "+f"(c[3])
        : "r"(a[0]), "r"(a[1]), "r"(a[2]), "r"(a[3]), "r"(b[0]), "r"(b[1]));
}

__device__ __forceinline__ void cp16(uint32_t dst_smem, const void* src) {
    asm volatile("cp.async.cg.shared.global [%0], [%1], 16;\n"
                 :: "r"(dst_smem), "l"(src));
}
#define CP_COMMIT() asm volatile("cp.async.commit_group;\n" ::: "memory")
#define CP_WAIT3()  asm volatile("cp.async.wait_group 3;\n" ::: "memory")
#define CP_WAIT1()  asm volatile("cp.async.wait_group 1;\n" ::: "memory")
#define CP_WAIT0()  asm volatile("cp.async.wait_group 0;\n" ::: "memory")

// ---------------- mbarrier / TMA (verified macro semantics) ------------------
#define MBARRIER_INIT(mbar_smem_addr, count) \
    asm volatile("mbarrier.init.shared.b64 [%0], %1;" \
                 :: "r"((uint32_t)(mbar_smem_addr)), "r"((uint32_t)(count)) \
                 : "memory")

#define MBARRIER_EXPECT_TX(mbar_smem_addr, tx_bytes) \
    asm volatile("mbarrier.arrive.expect_tx.shared.b64 _, [%0], %1;" \
                 :: "r"((uint32_t)(mbar_smem_addr)), "r"((uint32_t)(tx_bytes)) \
                 : "memory")

#define MBARRIER_WAIT_PARITY(mbar_smem_addr, phase_parity) do { \
    uint32_t _mbar = (uint32_t)(mbar_smem_addr); \
    uint32_t _parity = (uint32_t)(phase_parity); \
    uint32_t _done; \
    asm volatile( \
        "{\n\t" \
        ".reg .pred p;\n\t" \
        "mbarrier.try_wait.parity.acquire.cta.shared::cta.b64 p, [%1], %2;\n\t" \
        "selp.b32 %0, 1, 0, p;\n\t" \
        "}" \
        : "=r"(_done) : "r"(_mbar), "r"(_parity) : "memory"); \
    if (!_done) { \
        asm volatile( \
            "{\n\t" \
            ".reg .pred P1;\n\t" \
            "WAIT_LOOP_%=:\n\t" \
            "mbarrier.try_wait.parity.acquire.cta.shared::cta.b64 P1, [%0], %1, 0x989680;\n\t" \
            "@P1 bra.uni WAIT_DONE_%=;\n\t" \
            "bra.uni WAIT_LOOP_%=;\n\t" \
            "WAIT_DONE_%=:\n\t" \
            "}" \
            :: "r"(_mbar), "r"(_parity) : "memory"); \
    } \
} while(0)

__device__ __forceinline__ void tma2d(uint32_t dst, const CUtensorMap* m,
                                      int x, int y, uint32_t mbar) {
    asm volatile(
        "cp.async.bulk.tensor.2d.shared::cta.global.tile.mbarrier::complete_tx::bytes "
        "[%0], [%1, {%2, %3}], [%4];"
        :: "r"(dst), "l"(m), "r"(x), "r"(y), "r"(mbar) : "memory");
}

// ---------------- convert / transpose kernels (one-time) ---------------------
__global__ void cvt_x_kernel(const float4* __restrict__ src, int n4)
{
    uint2* dst = (uint2*)g_xh;
    for (int i = blockIdx.x * blockDim.x + threadIdx.x; i < n4;
         i += gridDim.x * blockDim.x) {
        float4 v = src[i];
        uint2 u;
        u.x = h2_bits(__floats2half2_rn(v.x, v.y));
        u.y = h2_bits(__floats2half2_rn(v.z, v.w));
        dst[i] = u;
    }
}

// src [R][C] fp32 -> dst [C][R] fp16
__global__ void transpose_cvt_kernel(const float* __restrict__ src,
                                     __half* __restrict__ dst, int R, int C)
{
    __shared__ float tile[32][33];
    const int bx = blockIdx.x * 32;
    const int by = blockIdx.y * 32;
    const int tx = threadIdx.x, ty = threadIdx.y;
#pragma unroll
    for (int j = 0; j < 32; j += 8)
        tile[ty + j][tx] = src[(size_t)(by + ty + j) * C + bx + tx];
    __syncthreads();
#pragma unroll
    for (int j = 0; j < 32; j += 8)
        dst[(size_t)(bx + ty + j) * R + by + tx] = __float2half(tile[tx][ty + j]);
}

// ---------------- FP16 GEMM: 256x128 CTA tile, 64x64 warp tile ---------------
// BK=64 halves. A [M,K] box 64x256 (32KB), B [N,K] box 64x128 (16KB), SW128.
// 4-stage TMA pipeline (or cp.async fallback), 1 CTA/SM.

#define TC_STAGES 4
#define A_STG 32768
#define B_STG 16384
#define STAGE_BYTES (A_STG + B_STG)           // 49152
#define GNT (KDIM / 64)                       // 16
#define TC_SMEM (TC_STAGES * STAGE_BYTES + 1024)   // 197632

template <bool USE_TMA>
__device__ __forceinline__ void stage_copy_cp(uint32_t stA,
                                              const __half* Asrc,
                                              const __half* Bsrc,
                                              int rowBase, int colBase,
                                              int kt, int tid)
{
    if (USE_TMA) return;
    // A: 256 rows x 8 chunks = 2048; B: 128 rows x 8 = 1024. 12 cp16/thread.
#pragma unroll
    for (int i = 0; i < 8; i++) {
        const int id = tid + i * 256;
        const int row = id >> 3;
        const int col = id & 7;
        cp16(stA + row * 128 + ((col ^ (row & 7)) << 4),
             Asrc + (size_t)(rowBase + row) * KDIM + kt * 64 + col * 8);
    }
#pragma unroll
    for (int i = 0; i < 4; i++) {
        const int id = tid + i * 256;
        const int row = id >> 3;
        const int col = id & 7;
        cp16(stA + A_STG + row * 128 + ((col ^ (row & 7)) << 4),
             Bsrc + (size_t)(colBase + row) * KDIM + kt * 64 + col * 8);
    }
    CP_COMMIT();
}

template <int NDIM, bool QKV, bool USE_TMA>
__global__ __launch_bounds__(256)
void gemm_sw_kernel(const CUtensorMap* __restrict__ pA,
                    const CUtensorMap* __restrict__ pB,
                    const __half* __restrict__ Asrc,
                    const __half* __restrict__ Bsrc,
                    const float* __restrict__ bias,
                    float* __restrict__ out)
{
    extern __shared__ uint8_t smraw[];
    __shared__ __align__(8) uint64_t mbars[TC_STAGES];
    const uint32_t tiles = (smem_u32(smraw) + 1023u) & ~1023u;

    const int tid = threadIdx.x;
    const int lane = tid & 31;
    const int wid = tid >> 5;
    const int warpM = wid & 3;          // 4 warps x 64 rows
    const int warpN = wid >> 2;         // 2 warps x 64 cols
    const int g   = lane >> 2;
    const int tig = lane & 3;

    const int rowBase = blockIdx.y * 256;
    const int colBase = blockIdx.x * 128;

    if (USE_TMA) {
        if (tid == 0) {
#pragma unroll
            for (int s = 0; s < TC_STAGES; s++)
                MBARRIER_INIT(smem_u32(&mbars[s]), 1);
        }
        __syncthreads();
        if (tid == 0) {
#pragma unroll
            for (int s = 0; s < TC_STAGES; s++) {
                const uint32_t mb = smem_u32(&mbars[s]);
                MBARRIER_EXPECT_TX(mb, STAGE_BYTES);
                tma2d(tiles + s * STAGE_BYTES,         pA, s * 64, rowBase, mb);
                tma2d(tiles + s * STAGE_BYTES + A_STG, pB, s * 64, colBase, mb);
            }
        }
    } else {
#pragma unroll
        for (int s = 0; s < TC_STAGES; s++)
            stage_copy_cp<USE_TMA>(tiles + s * STAGE_BYTES, Asrc, Bsrc,
                                   rowBase, colBase, s, tid);
    }

    // ldmatrix lane geometry (SW128: 16B chunk c -> c ^ (row&7))
    const int mat4 = lane >> 3;
    const int l8   = lane & 7;
    const int rA   = ((mat4 & 1) << 3) + l8;
    const int aSel = mat4 >> 1;
    const int bRowOff = ((mat4 >> 1) << 3) + l8;
    const int bSel = mat4 & 1;
    const uint32_t aRowBase = warpM * 64 + rA;
    const uint32_t bRowBase = warpN * 64 + bRowOff;

    float acc[4][8][4];
#pragma unroll
    for (int mt = 0; mt < 4; mt++)
#pragma unroll
        for (int nt = 0; nt < 8; nt++)
#pragma unroll
            for (int i = 0; i < 4; i++) acc[mt][nt][i] = 0.f;

    for (int kt = 0; kt < GNT; kt++) {
        const int s = kt % TC_STAGES;
        if (USE_TMA) {
            MBARRIER_WAIT_PARITY(smem_u32(&mbars[s]), (uint32_t)(kt / TC_STAGES) & 1u);
        } else {
            if (kt >= GNT - TC_STAGES) { CP_WAIT0(); } else { CP_WAIT3(); }
            __syncthreads();
        }

        const uint32_t stA = tiles + s * STAGE_BYTES;
        const uint32_t stB = stA + A_STG;

#pragma unroll
        for (int kc = 0; kc < 4; kc++) {
            uint32_t af[4][4];
#pragma unroll
            for (int mt = 0; mt < 4; mt++)
                ldm_x4(af[mt], stA + (aRowBase + mt * 16) * 128
                               + ((((kc << 1) + aSel) ^ l8) << 4));
            uint32_t bf[8][2];
#pragma unroll
            for (int ntp = 0; ntp < 4; ntp++) {
                uint32_t t4[4];
                ldm_x4(t4, stB + (bRowBase + ntp * 16) * 128
                           + ((((kc << 1) + bSel) ^ l8) << 4));
                bf[2 * ntp][0] = t4[0]; bf[2 * ntp][1] = t4[1];
                bf[2 * ntp + 1][0] = t4[2]; bf[2 * ntp + 1][1] = t4[3];
            }
#pragma unroll
            for (int mt = 0; mt < 4; mt++)
#pragma unroll
                for (int nt = 0; nt < 8; nt++)
                    mma_f16(acc[mt][nt], af[mt], bf[nt]);
        }
        __syncthreads();   // all warps done reading stage s

        if (kt + TC_STAGES < GNT) {
            if (USE_TMA) {
                if (tid == 0) {
                    const uint32_t mb = smem_u32(&mbars[s]);
                    MBARRIER_EXPECT_TX(mb, STAGE_BYTES);
                    tma2d(stA, pA, (kt + TC_STAGES) * 64, rowBase, mb);
                    tma2d(stB, pB, (kt + TC_STAGES) * 64, colBase, mb);
                }
            } else {
                stage_copy_cp<USE_TMA>(stA, Asrc, Bsrc, rowBase, colBase,
                                       kt + TC_STAGES, tid);
            }
        }
    }

    // ---------------- epilogue ----------------
#pragma unroll
    for (int mt = 0; mt < 4; mt++) {
        const int r0 = rowBase + warpM * 64 + mt * 16 + g;
        const int r1 = r0 + 8;
#pragma unroll
        for (int nt = 0; nt < 8; nt++) {
            const int c = colBase + warpN * 64 + nt * 8 + 2 * tig;
            const float b0 = bias[c];
            const float b1 = bias[c + 1];
            if (QKV) {
                const int which = c / Cd;
                const int inner = c % Cd;
                const int h = inner / HSd;
                const int d = inner % HSd;
                const float sc = (which == 0) ? 0.125f : 1.0f;
                __half* dst = (which == 0) ? g_Q : (which == 1) ? g_K : g_V;
                {
                    const int bb = r0 / Td, t = r0 % Td;
                    const size_t idx = ((size_t)(bb * NHd + h) * Td + t) * HSd + d;
                    *(__half2*)&dst[idx] =
                        __floats2half2_rn((acc[mt][nt][0] + b0) * sc,
                                          (acc[mt][nt][1] + b1) * sc);
                }
                {
                    const int bb = r1 / Td, t = r1 % Td;
                    const size_t idx = ((size_t)(bb * NHd + h) * Td + t) * HSd + d;
                    *(__half2*)&dst[idx] =
                        __floats2half2_rn((acc[mt][nt][2] + b0) * sc,
                                          (acc[mt][nt][3] + b1) * sc);
                }
            } else {
                float2 v0, v1;
                v0.x = acc[mt][nt][0] + b0;
                v0.y = acc[mt][nt][1] + b1;
                v1.x = acc[mt][nt][2] + b0;
                v1.y = acc[mt][nt][3] + b1;
                *(float2*)&out[(size_t)r0 * NDIM + c] = v0;
                *(float2*)&out[(size_t)r1 * NDIM + c] = v1;
            }
        }
    }
}

// ---------------- FP16 flash attention (unchanged from R13, passing) ---------
#define ATT_Q_OFF 0
#define ATT_K_OFF 18432
#define ATT_V_OFF 36864
#define ATT_STG   9216
#define ATT_SMEM  (55296 + 256)

__device__ __forceinline__ void attn_stage_kv(uint32_t ksS, uint32_t vsS,
                                              const __half* Kt,
                                              const __half* Vt, int tid)
{
#pragma unroll
    for (int i = 0; i < 2; i++) {
        const int id = tid + i * 256;       // chunk 0..511
        const int row = id >> 3;
        const int col = id & 7;
        cp16(ksS + row * 144 + col * 16, Kt + row * HSd + col * 8);
        cp16(vsS + row * 144 + col * 16, Vt + row * HSd + col * 8);
    }
    CP_COMMIT();
}

__global__ __launch_bounds__(256, 2)
void attn_f16_kernel()
{
    extern __shared__ uint8_t smraw[];
    const uint32_t base = (smem_u32(smraw) + 255u) & ~255u;
    const uint32_t qsB = base + ATT_Q_OFF;

    const int b = blockIdx.z;
    const int h = blockIdx.y;
    const int bx = gridDim.x - 1 - blockIdx.x;   // longest CTAs first
    const int qbase = bx * 128;

    const int tid  = threadIdx.x;
    const int lane = tid & 31;
    const int w    = tid >> 5;
    const int g    = lane >> 2;
    const int tig  = lane & 3;
    const int l8   = lane & 7;
    const int mat2 = (lane & 15) >> 3;
    const int hi   = lane >> 4;

    const size_t headOff = (size_t)(b * NHd + h) * Td * HSd;
    const __half* Kg = &g_K[headOff];
    const __half* Vg = &g_V[headOff];
    const __half* Qg = &g_Q[headOff + (size_t)qbase * HSd];

    const int ntiles = 2 * bx + 2;

    attn_stage_kv(base + ATT_K_OFF, base + ATT_V_OFF, Kg, Vg, tid);

#pragma unroll
    for (int j = 0; j < 4; j++) {
        const int f = tid + j * 256;
        const int r = f >> 3;
        const int c8 = (f & 7) << 3;
        *(uint4*)(smraw + (qsB - smem_u32(smraw)) + r * 144 + c8 * 2) =
            *(const uint4*)&Qg[r * HSd + c8];
    }
    __syncthreads();

    const int mat4 = lane >> 3;
    const int rQ   = w * 16 + ((mat4 & 1) << 3) + l8;
    const int cQ   = (mat4 >> 1) << 3;
    uint32_t qf[4][4];
#pragma unroll
    for (int kc = 0; kc < 4; kc++)
        ldm_x4(qf[kc], qsB + rQ * 144 + (kc * 16 + cQ) * 2);

    const int qrow0 = qbase + w * 16 + g;
    const int qrow1 = qrow0 + 8;

    float oacc[8][4];
#pragma unroll
    for (int nt = 0; nt < 8; nt++)
#pragma unroll
        for (int e = 0; e < 4; e++) oacc[nt][e] = 0.f;
    float m0 = -1e30f, m1 = -1e30f, l0 = 0.f, l1 = 0.f;

    for (int t = 0; t < ntiles; t++) {
        const uint32_t ksS = base + ATT_K_OFF + (t & 1) * ATT_STG;
        const uint32_t vsS = base + ATT_V_OFF + (t & 1) * ATT_STG;

        if (t + 1 < ntiles) {
            attn_stage_kv(base + ATT_K_OFF + ((t + 1) & 1) * ATT_STG,
                          base + ATT_V_OFF + ((t + 1) & 1) * ATT_STG,
                          Kg + (t + 1) * 64 * HSd, Vg + (t + 1) * 64 * HSd, tid);
            CP_WAIT1();
        } else {
            CP_WAIT0();
        }
        __syncthreads();

        float sacc[8][4];
#pragma unroll
        for (int nt = 0; nt < 8; nt++)
#pragma unroll
            for (int e = 0; e < 4; e++) sacc[nt][e] = 0.f;

#pragma unroll
        for (int kc = 0; kc < 4; kc++) {
#pragma unroll
            for (int ntp = 0; ntp < 4; ntp++) {
                uint32_t t4[4];
                ldm_x4(t4, ksS + (ntp * 16 + hi * 8 + l8) * 144
                           + (kc * 16 + mat2 * 8) * 2);
                uint32_t b0[2] = {t4[0], t4[1]};
                uint32_t b1[2] = {t4[2], t4[3]};
                mma_f16(sacc[2 * ntp], qf[kc], b0);
                mma_f16(sacc[2 * ntp + 1], qf[kc], b1);
            }
        }

        if (t >= 2 * bx) {
            const int colb = t * 64;
#pragma unroll
            for (int nt = 0; nt < 8; nt++) {
                const int c0 = colb + nt * 8 + 2 * tig;
                if (c0     > qrow0) sacc[nt][0] = -1e30f;
                if (c0 + 1 > qrow0) sacc[nt][1] = -1e30f;
                if (c0     > qrow1) sacc[nt][2] = -1e30f;
                if (c0 + 1 > qrow1) sacc[nt][3] = -1e30f;
            }
        }

        float mx0 = -1e30f, mx1 = -1e30f;
#pragma unroll
        for (int nt = 0; nt < 8; nt++) {
            mx0 = fmaxf(mx0, fmaxf(sacc[nt][0], sacc[nt][1]));
            mx1 = fmaxf(mx1, fmaxf(sacc[nt][2], sacc[nt][3]));
        }
        mx0 = fmaxf(mx0, __shfl_xor_sync(0xffffffffu, mx0, 1));
        mx0 = fmaxf(mx0, __shfl_xor_sync(0xffffffffu, mx0, 2));
        mx1 = fmaxf(mx1, __shfl_xor_sync(0xffffffffu, mx1, 1));
        mx1 = fmaxf(mx1, __shfl_xor_sync(0xffffffffu, mx1, 2));

        const float nm0 = fmaxf(m0, mx0);
        const float nm1 = fmaxf(m1, mx1);
        const float corr0 = __expf(m0 - nm0);
        const float corr1 = __expf(m1 - nm1);
        m0 = nm0; m1 = nm1;

        uint32_t ph0[8], ph1[8];
        float sum0 = 0.f, sum1 = 0.f;
#pragma unroll
        for (int nt = 0; nt < 8; nt++) {
            const float p0 = __expf(sacc[nt][0] - nm0);
            const float p1 = __expf(sacc[nt][1] - nm0);
            const float p2 = __expf(sacc[nt][2] - nm1);
            const float p3 = __expf(sacc[nt][3] - nm1);
            sum0 += p0 + p1;
            sum1 += p2 + p3;
            ph0[nt] = pack_h2(p0, p1);
            ph1[nt] = pack_h2(p2, p3);
            oacc[nt][0] *= corr0; oacc[nt][1] *= corr0;
            oacc[nt][2] *= corr1; oacc[nt][3] *= corr1;
        }
        l0 = l0 * corr0 + sum0;
        l1 = l1 * corr1 + sum1;

#pragma unroll
        for (int kc = 0; kc < 4; kc++) {
            uint32_t a[4] = {ph0[2 * kc], ph1[2 * kc],
                             ph0[2 * kc + 1], ph1[2 * kc + 1]};
#pragma unroll
            for (int ntp = 0; ntp < 4; ntp++) {
                uint32_t t4[4];
                ldm_x4t(t4, vsS + (kc * 16 + mat2 * 8 + l8) * 144
                            + (ntp * 2 + hi) * 16);
                uint32_t v0[2] = {t4[0], t4[1]};
                uint32_t v1[2] = {t4[2], t4[3]};
                mma_f16(oacc[2 * ntp], a, v0);
                mma_f16(oacc[2 * ntp + 1], a, v1);
            }
        }
        __syncthreads();
    }

    l0 += __shfl_xor_sync(0xffffffffu, l0, 1);
    l0 += __shfl_xor_sync(0xffffffffu, l0, 2);
    l1 += __shfl_xor_sync(0xffffffffu, l1, 1);
    l1 += __shfl_xor_sync(0xffffffffu, l1, 2);
    const float inv0 = 1.0f / l0;
    const float inv1 = 1.0f / l1;

    __half* y0 = &g_Y[((size_t)(b * Td + qrow0)) * Cd + h * HSd];
    __half* y1 = &g_Y[((size_t)(b * Td + qrow1)) * Cd + h * HSd];
#pragma unroll
    for (int nt = 0; nt < 8; nt++) {
        const int c = nt * 8 + 2 * tig;
        *(__half2*)&y0[c] = __floats2half2_rn(oacc[nt][0] * inv0,
                                              oacc[nt][1] * inv0);
        *(__half2*)&y1[c] = __floats2half2_rn(oacc[nt][2] * inv1,
                                              oacc[nt][3] * inv1);
    }
}

// ---------------- host launch ------------------------------------------------
typedef CUresult (*PFN_tmEncode)(
    CUtensorMap*, CUtensorMapDataType, cuuint32_t, void*,
    const cuuint64_t*, const cuuint64_t*, const cuuint32_t*, const cuuint32_t*,
    CUtensorMapInterleave, CUtensorMapSwizzle, CUtensorMapL2promotion,
    CUtensorMapFloatOOBfill);

static bool make_map(PFN_tmEncode enc, CUtensorMap* tm, void* base,
                     uint64_t rows, uint32_t rowBox)
{
    cuuint64_t dims[2]    = {(cuuint64_t)KDIM, (cuuint64_t)rows};
    cuuint64_t strides[1] = {(cuuint64_t)KDIM * 2};
    cuuint32_t box[2]     = {64, rowBox};
    cuuint32_t es[2]      = {1, 1};
    CUresult r = enc(tm, CU_TENSOR_MAP_DATA_TYPE_FLOAT16, 2, base, dims, strides,
                     box, es, CU_TENSOR_MAP_INTERLEAVE_NONE,
                     CU_TENSOR_MAP_SWIZZLE_128B,
                     CU_TENSOR_MAP_L2_PROMOTION_L2_128B,
                     CU_TENSOR_MAP_FLOAT_OOB_FILL_NONE);
    return r == CUDA_SUCCESS;
}

extern "C" void kernel_launch(void* const* d_in, const int* in_sizes, int n_in,
                              void* d_out, int out_size)
{
    const float* x      = (const float*)d_in[0];
    const float* W_attn = (const float*)d_in[1];
    const float* b_attn = (const float*)d_in[2];
    const float* W_proj = (const float*)d_in[3];
    const float* b_proj = (const float*)d_in[4];
    float* out = (float*)d_out;

    (void)in_sizes; (void)n_in; (void)out_size;

    void *p_xh, *p_wat, *p_wpt, *p_y;
    cudaGetSymbolAddress(&p_xh,  g_xh);
    cudaGetSymbolAddress(&p_wat, g_WAt);
    cudaGetSymbolAddress(&p_wpt, g_WPt);
    cudaGetSymbolAddress(&p_y,   g_Y);

    static CUtensorMap h_maps[4];
    bool use_tma = false;
    {
        void* fn = nullptr;
        cudaDriverEntryPointQueryResult qs =
            cudaDriverEntryPointSymbolNotFound;
        cudaError_t e = cudaGetDriverEntryPoint("cuTensorMapEncodeTiled", &fn,
                                                cudaEnableDefault, &qs);
        if (e == cudaSuccess && fn && qs == cudaDriverEntryPointSuccess) {
            PFN_tmEncode enc = (PFN_tmEncode)fn;
            bool ok = make_map(enc, &h_maps[0], p_xh,  Md,    256)
                   && make_map(enc, &h_maps[1], p_wat, N_QKV, 128)
                   && make_map(enc, &h_maps[2], p_wpt, Cd,    128)
                   && make_map(enc, &h_maps[3], p_y,   Md,    256);
            if (ok) {
                cudaMemcpyToSymbolAsync(d_tmaps, h_maps, sizeof(h_maps), 0,
                                        cudaMemcpyHostToDevice, 0);
                use_tma = true;
            }
        }
    }
    void* p_maps = nullptr;
    cudaGetSymbolAddress(&p_maps, d_tmaps);
    CUtensorMap* maps = (CUtensorMap*)p_maps;

    cudaFuncSetAttribute(gemm_sw_kernel<N_QKV, true, true>,
                         cudaFuncAttributeMaxDynamicSharedMemorySize, TC_SMEM);
    cudaFuncSetAttribute(gemm_sw_kernel<N_QKV, true, false>,
                         cudaFuncAttributeMaxDynamicSharedMemorySize, TC_SMEM);
    cudaFuncSetAttribute(gemm_sw_kernel<Cd, false, true>,
                         cudaFuncAttributeMaxDynamicSharedMemorySize, TC_SMEM);
    cudaFuncSetAttribute(gemm_sw_kernel<Cd, false, false>,
                         cudaFuncAttributeMaxDynamicSharedMemorySize, TC_SMEM);
    cudaFuncSetAttribute(attn_f16_kernel,
                         cudaFuncAttributeMaxDynamicSharedMemorySize, ATT_SMEM);

    cvt_x_kernel<<<4096, 256>>>((const float4*)x, Md * KDIM / 4);
    transpose_cvt_kernel<<<dim3(N_QKV / 32, KDIM / 32), dim3(32, 8)>>>(
        W_attn, (__half*)p_wat, KDIM, N_QKV);
    transpose_cvt_kernel<<<dim3(Cd / 32, KDIM / 32), dim3(32, 8)>>>(
        W_proj, (__half*)p_wpt, KDIM, Cd);

    dim3 gQKV(N_QKV / 128, Md / 256);     // (24, 32)
    dim3 gProj(Cd / 128, Md / 256);       // (8, 32)
    dim3 gAtt(Td / 128, NHd, Bd);         // (16, 16, 4)

    if (use_tma) {
        gemm_sw_kernel<N_QKV, true, true><<<gQKV, 256, TC_SMEM>>>(
            maps + 0, maps + 1, (const __half*)p_xh, (const __half*)p_wat,
            b_attn, nullptr);
        attn_f16_kernel<<<gAtt, 256, ATT_SMEM>>>();
        gemm_sw_kernel<Cd, false, true><<<gProj, 256, TC_SMEM>>>(
            maps + 3, maps + 2, (const __half*)p_y, (const __half*)p_wpt,
            b_proj, out);
    } else {
        gemm_sw_kernel<N_QKV, true, false><<<gQKV, 256, TC_SMEM>>>(
            nullptr, nullptr, (const __half*)p_xh, (const __half*)p_wat,
            b_attn, nullptr);
        attn_f16_kernel<<<gAtt, 256, ATT_SMEM>>>();
        gemm_sw_kernel<Cd, false, false><<<gProj, 256, TC_SMEM>>>(
            nullptr, nullptr, (const __half*)p_y, (const __half*)p_wpt,
            b_proj, out);
    }
}